// round 1
// baseline (speedup 1.0000x reference)
#include <cuda_runtime.h>
#include <math.h>

#define BB 16
#define LL 50
#define PP 49
#define TT 20
#define DD 512
#define HH 8
#define DHH 64
#define DFF 2048
#define NBL (BB*LL)            // 800
#define M_IMG (NBL*TT)         // 16000
#define M_TIT (NBL*PP)         // 39200
#define M_ALL (M_IMG+M_TIT)    // 55200
#define NEGV (-1000000000.0f)
#define STRIDE 516             // padded smem row stride (floats), %4==0

// Scratch (device globals: allocation-free rule)
__device__ float g_hidpre[(size_t)M_ALL*DD];   // attn out; later reused for ffn2 out
__device__ float g_hid[(size_t)M_ALL*DD];      // post-proj hidden (residual source)
__device__ float g_act[(size_t)M_ALL*DFF];     // ffn1 activations

// ---------------------------------------------------------------------------
// Kernel 1: per-(b,l) cross attention -> hid_pre (pre-projection)
// ---------------------------------------------------------------------------
__global__ __launch_bounds__(256) void attn_kernel(
    const float* __restrict__ img, const float* __restrict__ title,
    const int* __restrict__ mask, const float* __restrict__ scale_img,
    const float* __restrict__ scale_tit, float* __restrict__ hid_pre)
{
    extern __shared__ float sm[];
    float* s_img = sm;                        // PP*STRIDE
    float* s_tit = s_img + PP*STRIDE;         // TT*STRIDE
    float* s_raw = s_tit + TT*STRIDE;         // HH*PP*TT
    float* s_p   = s_raw + HH*PP*TT;          // HH*PP*TT (reused p_img then p_tit)
    float* s_si  = s_p  + HH*PP*TT;           // HH*PP
    float* s_st  = s_si + HH*PP;              // HH*TT
    int*   s_mask= (int*)(s_st + HH*TT);      // TT

    int bl  = blockIdx.x;
    int tid = threadIdx.x;

    // ---- cooperative loads (float4, padded smem rows) ----
    const float* gi = img + (size_t)bl*PP*DD;
    for (int i = tid; i < PP*(DD/4); i += 256){
        int r = i >> 7, c = i & 127;
        float4 v = ((const float4*)(gi + (size_t)r*DD))[c];
        *(float4*)(s_img + r*STRIDE + c*4) = v;
    }
    const float* gt = title + (size_t)bl*TT*DD;
    for (int i = tid; i < TT*(DD/4); i += 256){
        int r = i >> 7, c = i & 127;
        float4 v = ((const float4*)(gt + (size_t)r*DD))[c];
        *(float4*)(s_tit + r*STRIDE + c*4) = v;
    }
    for (int i = tid; i < HH*PP; i += 256) s_si[i] = scale_img[i];
    for (int i = tid; i < HH*TT; i += 256) s_st[i] = scale_tit[i];
    if (tid < TT) s_mask[tid] = mask[bl*TT + tid];
    __syncthreads();

    // ---- raw[h][p][t] = (imgh[p,h,:] . tith[t,h,:]) / 8 ----
    for (int pair = tid; pair < HH*PP; pair += 256){
        int h = pair / PP, p = pair % PP;
        float acc[TT];
        #pragma unroll
        for (int t=0;t<TT;t++) acc[t]=0.f;
        const float* ib = s_img + p*STRIDE + h*DHH;
        const float* tb = s_tit + h*DHH;
        #pragma unroll 4
        for (int d=0; d<DHH; d++){
            float a = ib[d];
            #pragma unroll
            for (int t=0;t<TT;t++) acc[t] += a * tb[t*STRIDE + d];
        }
        float* rw = s_raw + pair*TT;
        #pragma unroll
        for (int t=0;t<TT;t++) rw[t] = acc[t]*0.125f;
    }
    __syncthreads();

    // ---- p_img = softmax_t( mask ? raw*scale_img[h,p] : NEG ) ----
    for (int pair = tid; pair < HH*PP; pair += 256){
        float sc = s_si[pair];
        const float* rw = s_raw + pair*TT;
        float v[TT]; float m = -3.4e38f;
        #pragma unroll
        for (int t=0;t<TT;t++){
            v[t] = (s_mask[t]==0) ? NEGV : rw[t]*sc;
            m = fmaxf(m, v[t]);
        }
        float s = 0.f;
        #pragma unroll
        for (int t=0;t<TT;t++){ v[t] = expf(v[t]-m); s += v[t]; }
        float inv = 1.f/s;
        float* pw = s_p + pair*TT;
        #pragma unroll
        for (int t=0;t<TT;t++) pw[t] = v[t]*inv;
    }
    __syncthreads();

    // ---- hid_tit[p][col] = sum_t p_img[h,p,t] * title[t][col] ----
    for (int idx = tid; idx < PP*(DD/4); idx += 256){
        int p = idx >> 7, c = idx & 127;
        int col = c*4; int h = col >> 6;
        const float* pw = s_p + (h*PP + p)*TT;
        float4 acc = make_float4(0.f,0.f,0.f,0.f);
        #pragma unroll
        for (int t=0;t<TT;t++){
            float w = pw[t];
            float4 v = *(const float4*)(s_tit + t*STRIDE + col);
            acc.x += w*v.x; acc.y += w*v.y; acc.z += w*v.z; acc.w += w*v.w;
        }
        *(float4*)(hid_pre + (size_t)(M_IMG + bl*PP + p)*DD + col) = acc;
    }
    __syncthreads();

    // ---- p_tit[h][t][p] = softmax_p( mask[t] ? raw^T*scale_tit[h,t] : NEG ) ----
    for (int idx = tid; idx < HH*TT; idx += 256){
        int h = idx / TT, t = idx % TT;
        float sc = s_st[idx];
        bool mz = (s_mask[t]==0);
        const float* rw = s_raw + h*PP*TT + t;   // stride TT over p
        float m = -3.4e38f;
        for (int p=0;p<PP;p++){
            float v = mz ? NEGV : rw[p*TT]*sc;
            m = fmaxf(m, v);
        }
        float* pw = s_p + (h*TT + t)*PP;
        float s = 0.f;
        for (int p=0;p<PP;p++){
            float v = mz ? NEGV : rw[p*TT]*sc;
            float e = expf(v-m);
            pw[p] = e; s += e;
        }
        float inv = 1.f/s;
        for (int p=0;p<PP;p++) pw[p] *= inv;
    }
    __syncthreads();

    // ---- hid_img[t][col] = sum_p p_tit[h,t,p] * img[p][col] ----
    for (int idx = tid; idx < TT*(DD/4); idx += 256){
        int t = idx >> 7, c = idx & 127;
        int col = c*4; int h = col >> 6;
        const float* pw = s_p + (h*TT + t)*PP;
        float4 acc = make_float4(0.f,0.f,0.f,0.f);
        for (int p=0;p<PP;p++){
            float w = pw[p];
            float4 v = *(const float4*)(s_img + p*STRIDE + col);
            acc.x += w*v.x; acc.y += w*v.y; acc.z += w*v.z; acc.w += w*v.w;
        }
        *(float4*)(hid_pre + (size_t)(bl*TT + t)*DD + col) = acc;
    }
}

// ---------------------------------------------------------------------------
// Kernel 2: SGEMM C[M,N] = A[M,K] @ B[N,K]^T + bias, optional tanh-GELU.
// 128x128 tile, BK=8, 256 threads, 8x8 per thread.
// ---------------------------------------------------------------------------
__device__ __forceinline__ float gelu_tanh_f(float x){
    return 0.5f*x*(1.f + tanhf(0.7978845608028654f*(x + 0.044715f*x*x*x)));
}

template<bool GELU>
__global__ __launch_bounds__(256) void sgemm_nt(
    const float* __restrict__ A, const float* __restrict__ Bm,
    const float* __restrict__ bias, float* __restrict__ C,
    int M, int N, int K)
{
    __shared__ float As[8][128];
    __shared__ float Bs[8][128];
    int tid = threadIdx.x;
    int tx = tid & 15, ty = tid >> 4;
    int rowBase = blockIdx.y * 128, colBase = blockIdx.x * 128;
    int lRow = tid >> 1;
    int lK   = (tid & 1) * 4;
    const float* Ap = A  + (size_t)(rowBase + lRow)*K + lK;
    const float* Bp = Bm + (size_t)(colBase + lRow)*K + lK;
    bool aOk = (rowBase + lRow) < M;

    float acc[8][8];
    #pragma unroll
    for (int i=0;i<8;i++)
        #pragma unroll
        for (int j=0;j<8;j++) acc[i][j]=0.f;

    for (int k0=0; k0<K; k0+=8){
        float4 av = aOk ? *(const float4*)(Ap + k0) : make_float4(0.f,0.f,0.f,0.f);
        float4 bv = *(const float4*)(Bp + k0);
        __syncthreads();
        As[lK+0][lRow]=av.x; As[lK+1][lRow]=av.y; As[lK+2][lRow]=av.z; As[lK+3][lRow]=av.w;
        Bs[lK+0][lRow]=bv.x; Bs[lK+1][lRow]=bv.y; Bs[lK+2][lRow]=bv.z; Bs[lK+3][lRow]=bv.w;
        __syncthreads();
        #pragma unroll
        for (int kk=0;kk<8;kk++){
            float a[8], b[8];
            *(float4*)&a[0] = *(const float4*)&As[kk][ty*8];
            *(float4*)&a[4] = *(const float4*)&As[kk][ty*8+4];
            *(float4*)&b[0] = *(const float4*)&Bs[kk][tx*8];
            *(float4*)&b[4] = *(const float4*)&Bs[kk][tx*8+4];
            #pragma unroll
            for (int i=0;i<8;i++)
                #pragma unroll
                for (int j=0;j<8;j++)
                    acc[i][j] += a[i]*b[j];
        }
    }

    float bias8[8];
    *(float4*)&bias8[0] = *(const float4*)&bias[colBase + tx*8];
    *(float4*)&bias8[4] = *(const float4*)&bias[colBase + tx*8 + 4];
    #pragma unroll
    for (int i=0;i<8;i++){
        int r = rowBase + ty*8 + i;
        if (r < M){
            float o[8];
            #pragma unroll
            for (int j=0;j<8;j++){
                float v = acc[i][j] + bias8[j];
                if (GELU) v = gelu_tanh_f(v);
                o[j] = v;
            }
            float* Cp = C + (size_t)r*N + colBase + tx*8;
            *(float4*)&Cp[0] = *(float4*)&o[0];
            *(float4*)&Cp[4] = *(float4*)&o[4];
        }
    }
}

// ---------------------------------------------------------------------------
// Kernel 3: out = hid + a*(x-mean)/(std(ddof=1)+eps) + b   (row-wise, D=512)
// ---------------------------------------------------------------------------
__device__ __forceinline__ float blockReduce128(float v){
    __shared__ float red[4];
    int lane = threadIdx.x & 31, w = threadIdx.x >> 5;
    #pragma unroll
    for (int o=16;o>0;o>>=1) v += __shfl_down_sync(0xffffffffu, v, o);
    if (lane==0) red[w]=v;
    __syncthreads();
    float r = red[0]+red[1]+red[2]+red[3];
    __syncthreads();
    return r;
}

__global__ __launch_bounds__(128) void ln_res_kernel(
    const float* __restrict__ ffn, const float* __restrict__ hid,
    const float* __restrict__ a_img, const float* __restrict__ b_img,
    const float* __restrict__ a_tit, const float* __restrict__ b_tit,
    float* __restrict__ out)
{
    int row = blockIdx.x; int tid = threadIdx.x;
    float4 v = ((const float4*)(ffn + (size_t)row*DD))[tid];
    float s = v.x+v.y+v.z+v.w;
    float tot = blockReduce128(s);
    float mean = tot * (1.f/DD);
    float dx=v.x-mean, dy=v.y-mean, dz=v.z-mean, dw=v.w-mean;
    float sq = dx*dx+dy*dy+dz*dz+dw*dw;
    float tsq = blockReduce128(sq);
    float var = tsq * (1.f/(DD-1));
    float inv = 1.f/(sqrtf(var)+1e-6f);
    const float* ga = (row < M_IMG)? a_img : a_tit;
    const float* gb = (row < M_IMG)? b_img : b_tit;
    float4 av = ((const float4*)ga)[tid];
    float4 bv = ((const float4*)gb)[tid];
    float4 hv = ((const float4*)(hid + (size_t)row*DD))[tid];
    float4 o;
    o.x = hv.x + av.x*dx*inv + bv.x;
    o.y = hv.y + av.y*dy*inv + bv.y;
    o.z = hv.z + av.z*dz*inv + bv.z;
    o.w = hv.w + av.w*dw*inv + bv.w;
    ((float4*)(out + (size_t)row*DD))[tid] = o;
}

// ---------------------------------------------------------------------------
extern "C" void kernel_launch(void* const* d_in, const int* in_sizes, int n_in,
                              void* d_out, int out_size)
{
    const float* img       = (const float*)d_in[0];
    const float* title     = (const float*)d_in[1];
    const int*   mask      = (const int*)  d_in[2];
    const float* scale_img = (const float*)d_in[3];
    const float* scale_tit = (const float*)d_in[4];
    const float* w_proj    = (const float*)d_in[5];
    const float* b_proj    = (const float*)d_in[6];
    const float* w1_img    = (const float*)d_in[7];
    const float* b1_img    = (const float*)d_in[8];
    const float* w2_img    = (const float*)d_in[9];
    const float* b2_img    = (const float*)d_in[10];
    const float* w1_tit    = (const float*)d_in[11];
    const float* b1_tit    = (const float*)d_in[12];
    const float* w2_tit    = (const float*)d_in[13];
    const float* b2_tit    = (const float*)d_in[14];
    const float* ln_a_img  = (const float*)d_in[15];
    const float* ln_b_img  = (const float*)d_in[16];
    const float* ln_a_tit  = (const float*)d_in[17];
    const float* ln_b_tit  = (const float*)d_in[18];
    float* out = (float*)d_out;

    float *hidpre, *hid, *act;
    cudaGetSymbolAddress((void**)&hidpre, g_hidpre);
    cudaGetSymbolAddress((void**)&hid,    g_hid);
    cudaGetSymbolAddress((void**)&act,    g_act);

    const int attn_smem = (PP*STRIDE + TT*STRIDE + 2*HH*PP*TT + HH*PP + HH*TT)*4 + TT*4;
    cudaFuncSetAttribute(attn_kernel, cudaFuncAttributeMaxDynamicSharedMemorySize, attn_smem);

    // 1) attention -> hid_pre (img rows [0,16000), tit rows [16000,55200))
    attn_kernel<<<NBL, 256, attn_smem>>>(img, title, mask, scale_img, scale_tit, hidpre);

    // 2) shared projection over combined matrix
    sgemm_nt<false><<<dim3(DD/128, (M_ALL+127)/128), 256>>>(hidpre, w_proj, b_proj, hid, M_ALL, DD, DD);

    // 3) FFN1 + gelu (separate weights per stream)
    sgemm_nt<true><<<dim3(DFF/128, (M_IMG+127)/128), 256>>>(hid, w1_img, b1_img, act, M_IMG, DFF, DD);
    sgemm_nt<true><<<dim3(DFF/128, (M_TIT+127)/128), 256>>>(hid + (size_t)M_IMG*DD, w1_tit, b1_tit,
                                                            act + (size_t)M_IMG*DFF, M_TIT, DFF, DD);

    // 4) FFN2 -> reuse hidpre as ffn output buffer
    sgemm_nt<false><<<dim3(DD/128, (M_IMG+127)/128), 256>>>(act, w2_img, b2_img, hidpre, M_IMG, DD, DFF);
    sgemm_nt<false><<<dim3(DD/128, (M_TIT+127)/128), 256>>>(act + (size_t)M_IMG*DFF, w2_tit, b2_tit,
                                                            hidpre + (size_t)M_IMG*DD, M_TIT, DD, DFF);

    // 5) residual + layernorm -> out (out_img then out_tit, contiguous)
    ln_res_kernel<<<M_ALL, 128>>>(hidpre, hid, ln_a_img, ln_b_img, ln_a_tit, ln_b_tit, out);
}

// round 14
// speedup vs baseline: 2.5132x; 2.5132x over previous
#include <cuda_runtime.h>
#include <cuda_bf16.h>
#include <math.h>
#include <stdint.h>

#define BB 16
#define LL 50
#define PP 49
#define TT 20
#define DD 512
#define HH 8
#define DHH 64
#define DFF 2048
#define NBL (BB*LL)            // 800
#define M_IMG (NBL*TT)         // 16000 (=125*128)
#define M_TIT (NBL*PP)         // 39200
#define M_ALL (M_IMG+M_TIT)    // 55200
#define M_TITP 39296           // pad to 128
#define M_ALLP 55296           // = 432*128
#define NEGV (-1000000000.0f)
#define STRIDE 516
#define LDA 40                 // smem row stride in bf16 elems (32 data + 8 pad)

// ---------------- scratch (device globals, zero-init) ----------------------
__device__ float g_hidpre[(size_t)M_ALLP*DD];   // attn out; later ffn2 out
__device__ float g_hid[(size_t)M_ALLP*DD];      // post-proj hidden (residual)
__device__ float g_act[(size_t)M_ALLP*DFF];     // ffn1 activations

// ---------------- helpers ----------------------------------------------------
__device__ __forceinline__ uint32_t smem_u32(const void* p){
    uint32_t a;
    asm("{ .reg .u64 t; cvta.to.shared.u64 t, %1; cvt.u32.u64 %0, t; }"
        : "=r"(a) : "l"(p));
    return a;
}
__device__ __forceinline__ void ldsm_x4(uint32_t addr, uint32_t& r0, uint32_t& r1,
                                        uint32_t& r2, uint32_t& r3){
    asm volatile("ldmatrix.sync.aligned.m8n8.x4.shared.b16 {%0,%1,%2,%3}, [%4];"
                 : "=r"(r0), "=r"(r1), "=r"(r2), "=r"(r3) : "r"(addr));
}
__device__ __forceinline__ void mma16816(float* c, const uint32_t* a, const uint32_t* b){
    asm volatile(
        "mma.sync.aligned.m16n8k16.row.col.f32.bf16.bf16.f32 "
        "{%0,%1,%2,%3}, {%4,%5,%6,%7}, {%8,%9}, {%0,%1,%2,%3};"
        : "+f"(c[0]), "+f"(c[1]), "+f"(c[2]), "+f"(c[3])
        : "r"(a[0]), "r"(a[1]), "r"(a[2]), "r"(a[3]), "r"(b[0]), "r"(b[1]));
}
__device__ __forceinline__ void split2(float x, unsigned short& h, unsigned short& l){
    __nv_bfloat16 bh = __float2bfloat16(x);
    float r = x - __bfloat162float(bh);
    __nv_bfloat16 bl = __float2bfloat16(r);
    h = *(unsigned short*)&bh;
    l = *(unsigned short*)&bl;
}
__device__ __forceinline__ float gelu_tanh_f(float x){
    return 0.5f*x*(1.f + tanhf(0.7978845608028654f*(x + 0.044715f*x*x*x)));
}

// ---------------- bf16x3 GEMM via mma.sync: C = A[M,K]@B[N,K]^T + bias ------
// CTA tile 128x128, BK=32 fp32/chunk, 8 warps (4M x 2N), warp tile 32x64.
template<bool GELU>
__global__ __launch_bounds__(256, 2) void mma_gemm_k(
    const float* __restrict__ A, const float* __restrict__ Bw,
    const float* __restrict__ bias, float* __restrict__ C,
    int K, int ldc)
{
    __shared__ __align__(16) unsigned short sA[2][128*LDA];  // [hi/lo]
    __shared__ __align__(16) unsigned short sB[2][128*LDA];

    int tid = threadIdx.x;
    int lane = tid & 31, wid = tid >> 5;
    int wm = wid & 3, wn = wid >> 2;
    int g = lane >> 3, r = lane & 7;

    // ldmatrix lane address offsets (bytes, relative to array base)
    // A: groups g0: (m+0..7, k0) g1: (m+8..15, k0) g2: (m+0..7, k8) g3: (m+8..15, k8)
    uint32_t a_off = (uint32_t)((wm*32 + ((g & 1) << 3) + r)*LDA + ((g >> 1) << 3)) * 2u;
    // B: g0: (n+0..7, k0) g1: (n+0..7, k8) g2: (n+8..15, k0) g3: (n+8..15, k8)
    uint32_t b_off = (uint32_t)((wn*64 + ((g & 2) << 2) + r)*LDA + ((g & 1) << 3)) * 2u;

    uint32_t aHi = smem_u32(&sA[0][0]) + a_off;
    uint32_t aLo = smem_u32(&sA[1][0]) + a_off;
    uint32_t bHi = smem_u32(&sB[0][0]) + b_off;
    uint32_t bLo = smem_u32(&sB[1][0]) + b_off;

    const float* Ab = A + (size_t)(blockIdx.y << 7)*K;
    const float* Bb = Bw + (size_t)(blockIdx.x << 7)*K;

    float acc[2][8][4];
    #pragma unroll
    for (int mt=0; mt<2; mt++)
        #pragma unroll
        for (int nt=0; nt<8; nt++)
            #pragma unroll
            for (int j=0; j<4; j++) acc[mt][nt][j] = 0.f;

    for (int k0 = 0; k0 < K; k0 += 32){
        // ---- stage A,B chunk: fp32 -> bf16 hi/lo ----
        #pragma unroll
        for (int i=0; i<4; i++){
            int f4 = tid + (i << 8);
            int row = f4 >> 3;
            int kk = (f4 & 7) << 2;
            float4 v = *(const float4*)(Ab + (size_t)row*K + k0 + kk);
            unsigned short h0,h1,h2,h3,l0,l1,l2,l3;
            split2(v.x,h0,l0); split2(v.y,h1,l1); split2(v.z,h2,l2); split2(v.w,h3,l3);
            uint2 H, L;
            H.x = (uint32_t)h0 | ((uint32_t)h1<<16); H.y = (uint32_t)h2 | ((uint32_t)h3<<16);
            L.x = (uint32_t)l0 | ((uint32_t)l1<<16); L.y = (uint32_t)l2 | ((uint32_t)l3<<16);
            int off = row*LDA + kk;
            *(uint2*)(&sA[0][off]) = H;
            *(uint2*)(&sA[1][off]) = L;
        }
        #pragma unroll
        for (int i=0; i<4; i++){
            int f4 = tid + (i << 8);
            int row = f4 >> 3;
            int kk = (f4 & 7) << 2;
            float4 v = *(const float4*)(Bb + (size_t)row*K + k0 + kk);
            unsigned short h0,h1,h2,h3,l0,l1,l2,l3;
            split2(v.x,h0,l0); split2(v.y,h1,l1); split2(v.z,h2,l2); split2(v.w,h3,l3);
            uint2 H, L;
            H.x = (uint32_t)h0 | ((uint32_t)h1<<16); H.y = (uint32_t)h2 | ((uint32_t)h3<<16);
            L.x = (uint32_t)l0 | ((uint32_t)l1<<16); L.y = (uint32_t)l2 | ((uint32_t)l3<<16);
            int off = row*LDA + kk;
            *(uint2*)(&sB[0][off]) = H;
            *(uint2*)(&sB[1][off]) = L;
        }
        __syncthreads();

        // ---- compute: 2 k16-steps ----
        #pragma unroll
        for (int ks=0; ks<2; ks++){
            uint32_t kofs = (uint32_t)ks * 32u;      // 16 bf16 = 32B
            uint32_t a_h[2][4], a_l[2][4];
            ldsm_x4(aHi + kofs,        a_h[0][0], a_h[0][1], a_h[0][2], a_h[0][3]);
            ldsm_x4(aHi + kofs + 1280, a_h[1][0], a_h[1][1], a_h[1][2], a_h[1][3]); // +16 rows
            ldsm_x4(aLo + kofs,        a_l[0][0], a_l[0][1], a_l[0][2], a_l[0][3]);
            ldsm_x4(aLo + kofs + 1280, a_l[1][0], a_l[1][1], a_l[1][2], a_l[1][3]);

            #pragma unroll
            for (int nh=0; nh<2; nh++){
                uint32_t b_h[4][2], b_l[4][2];
                #pragma unroll
                for (int p=0; p<2; p++){
                    uint32_t boff2 = kofs + (uint32_t)(nh*2 + p) * 1280u; // 16 n-rows
                    ldsm_x4(bHi + boff2, b_h[2*p][0], b_h[2*p][1], b_h[2*p+1][0], b_h[2*p+1][1]);
                    ldsm_x4(bLo + boff2, b_l[2*p][0], b_l[2*p][1], b_l[2*p+1][0], b_l[2*p+1][1]);
                }
                #pragma unroll
                for (int mt=0; mt<2; mt++)
                    #pragma unroll
                    for (int ntl=0; ntl<4; ntl++){
                        float* c = acc[mt][nh*4 + ntl];
                        mma16816(c, a_h[mt], b_h[ntl]);
                        mma16816(c, a_h[mt], b_l[ntl]);
                        mma16816(c, a_l[mt], b_h[ntl]);
                    }
            }
        }
        __syncthreads();
    }

    // ---- epilogue ----
    int mbase = (blockIdx.y << 7) + wm*32;
    int nbase = (blockIdx.x << 7) + wn*64;
    int qr = lane >> 2;
    int qc = (lane & 3) << 1;
    #pragma unroll
    for (int mt=0; mt<2; mt++){
        #pragma unroll
        for (int nt=0; nt<8; nt++){
            int row = mbase + mt*16 + qr;
            int col = nbase + nt*8 + qc;
            float b0 = bias[col], b1 = bias[col+1];
            float v0 = acc[mt][nt][0] + b0;
            float v1 = acc[mt][nt][1] + b1;
            float v2 = acc[mt][nt][2] + b0;
            float v3 = acc[mt][nt][3] + b1;
            if (GELU){
                v0 = gelu_tanh_f(v0); v1 = gelu_tanh_f(v1);
                v2 = gelu_tanh_f(v2); v3 = gelu_tanh_f(v3);
            }
            *(float2*)(C + (size_t)row*ldc + col)     = make_float2(v0, v1);
            *(float2*)(C + (size_t)(row+8)*ldc + col) = make_float2(v2, v3);
        }
    }
}

// ---------------- zero pad rows of hidpre -----------------------------------
__global__ void zero_pad_k(float* p){
    size_t i = (size_t)blockIdx.x*512 + threadIdx.x;
    p[(size_t)M_ALL*DD + i] = 0.f;
}

// ---------------- Kernel 1: per-(b,l) cross attention -----------------------
__global__ __launch_bounds__(256) void attn_kernel(
    const float* __restrict__ img, const float* __restrict__ title,
    const int* __restrict__ mask, const float* __restrict__ scale_img,
    const float* __restrict__ scale_tit, float* __restrict__ hid_pre)
{
    extern __shared__ float sm[];
    float* s_img = sm;                        // PP*STRIDE
    float* s_tit = s_img + PP*STRIDE;         // TT*STRIDE
    float* s_raw = s_tit + TT*STRIDE;         // HH*PP*TT
    float* s_p   = s_raw + HH*PP*TT;          // HH*PP*TT
    float* s_si  = s_p  + HH*PP*TT;           // HH*PP
    float* s_st  = s_si + HH*PP;              // HH*TT
    int*   s_mask= (int*)(s_st + HH*TT);      // TT

    int bl  = blockIdx.x;
    int tid = threadIdx.x;

    const float* gi = img + (size_t)bl*PP*DD;
    for (int i = tid; i < PP*(DD/4); i += 256){
        int r = i >> 7, c = i & 127;
        float4 v = ((const float4*)(gi + (size_t)r*DD))[c];
        *(float4*)(s_img + r*STRIDE + c*4) = v;
    }
    const float* gt = title + (size_t)bl*TT*DD;
    for (int i = tid; i < TT*(DD/4); i += 256){
        int r = i >> 7, c = i & 127;
        float4 v = ((const float4*)(gt + (size_t)r*DD))[c];
        *(float4*)(s_tit + r*STRIDE + c*4) = v;
    }
    for (int i = tid; i < HH*PP; i += 256) s_si[i] = scale_img[i];
    for (int i = tid; i < HH*TT; i += 256) s_st[i] = scale_tit[i];
    if (tid < TT) s_mask[tid] = mask[bl*TT + tid];
    __syncthreads();

    for (int pair = tid; pair < HH*PP; pair += 256){
        int h = pair / PP, p = pair % PP;
        float acc[TT];
        #pragma unroll
        for (int t=0;t<TT;t++) acc[t]=0.f;
        const float* ib = s_img + p*STRIDE + h*DHH;
        const float* tb = s_tit + h*DHH;
        #pragma unroll 4
        for (int d=0; d<DHH; d++){
            float a = ib[d];
            #pragma unroll
            for (int t=0;t<TT;t++) acc[t] += a * tb[t*STRIDE + d];
        }
        float* rw = s_raw + pair*TT;
        #pragma unroll
        for (int t=0;t<TT;t++) rw[t] = acc[t]*0.125f;
    }
    __syncthreads();

    for (int pair = tid; pair < HH*PP; pair += 256){
        float sc = s_si[pair];
        const float* rw = s_raw + pair*TT;
        float v[TT]; float m = -3.4e38f;
        #pragma unroll
        for (int t=0;t<TT;t++){
            v[t] = (s_mask[t]==0) ? NEGV : rw[t]*sc;
            m = fmaxf(m, v[t]);
        }
        float s = 0.f;
        #pragma unroll
        for (int t=0;t<TT;t++){ v[t] = expf(v[t]-m); s += v[t]; }
        float inv = 1.f/s;
        float* pw = s_p + pair*TT;
        #pragma unroll
        for (int t=0;t<TT;t++) pw[t] = v[t]*inv;
    }
    __syncthreads();

    for (int idx = tid; idx < PP*(DD/4); idx += 256){
        int p = idx >> 7, c = idx & 127;
        int col = c*4; int h = col >> 6;
        const float* pw = s_p + (h*PP + p)*TT;
        float4 acc = make_float4(0.f,0.f,0.f,0.f);
        #pragma unroll
        for (int t=0;t<TT;t++){
            float w = pw[t];
            float4 v = *(const float4*)(s_tit + t*STRIDE + col);
            acc.x += w*v.x; acc.y += w*v.y; acc.z += w*v.z; acc.w += w*v.w;
        }
        *(float4*)(hid_pre + (size_t)(M_IMG + bl*PP + p)*DD + col) = acc;
    }
    __syncthreads();

    for (int idx = tid; idx < HH*TT; idx += 256){
        int h = idx / TT, t = idx % TT;
        float sc = s_st[idx];
        bool mz = (s_mask[t]==0);
        const float* rw = s_raw + h*PP*TT + t;
        float m = -3.4e38f;
        for (int p=0;p<PP;p++){
            float v = mz ? NEGV : rw[p*TT]*sc;
            m = fmaxf(m, v);
        }
        float* pw = s_p + (h*TT + t)*PP;
        float s = 0.f;
        for (int p=0;p<PP;p++){
            float v = mz ? NEGV : rw[p*TT]*sc;
            float e = expf(v-m);
            pw[p] = e; s += e;
        }
        float inv = 1.f/s;
        for (int p=0;p<PP;p++) pw[p] *= inv;
    }
    __syncthreads();

    for (int idx = tid; idx < TT*(DD/4); idx += 256){
        int t = idx >> 7, c = idx & 127;
        int col = c*4; int h = col >> 6;
        const float* pw = s_p + (h*TT + t)*PP;
        float4 acc = make_float4(0.f,0.f,0.f,0.f);
        for (int p=0;p<PP;p++){
            float w = pw[p];
            float4 v = *(const float4*)(s_img + p*STRIDE + col);
            acc.x += w*v.x; acc.y += w*v.y; acc.z += w*v.z; acc.w += w*v.w;
        }
        *(float4*)(hid_pre + (size_t)(bl*TT + t)*DD + col) = acc;
    }
}

// ---------------- Kernel 3: residual + layernorm ----------------------------
__device__ __forceinline__ float blockReduce128(float v){
    __shared__ float red[4];
    int lane = threadIdx.x & 31, w = threadIdx.x >> 5;
    #pragma unroll
    for (int o=16;o>0;o>>=1) v += __shfl_down_sync(0xffffffffu, v, o);
    if (lane==0) red[w]=v;
    __syncthreads();
    float r = red[0]+red[1]+red[2]+red[3];
    __syncthreads();
    return r;
}

__global__ __launch_bounds__(128) void ln_res_kernel(
    const float* __restrict__ ffn, const float* __restrict__ hid,
    const float* __restrict__ a_img, const float* __restrict__ b_img,
    const float* __restrict__ a_tit, const float* __restrict__ b_tit,
    float* __restrict__ out)
{
    int row = blockIdx.x; int tid = threadIdx.x;
    float4 v = ((const float4*)(ffn + (size_t)row*DD))[tid];
    float s = v.x+v.y+v.z+v.w;
    float tot = blockReduce128(s);
    float mean = tot * (1.f/DD);
    float dx=v.x-mean, dy=v.y-mean, dz=v.z-mean, dw=v.w-mean;
    float sq = dx*dx+dy*dy+dz*dz+dw*dw;
    float tsq = blockReduce128(sq);
    float var = tsq * (1.f/(DD-1));
    float inv = 1.f/(sqrtf(var)+1e-6f);
    const float* ga = (row < M_IMG)? a_img : a_tit;
    const float* gb = (row < M_IMG)? b_img : b_tit;
    float4 av = ((const float4*)ga)[tid];
    float4 bv = ((const float4*)gb)[tid];
    float4 hv = ((const float4*)(hid + (size_t)row*DD))[tid];
    float4 o;
    o.x = hv.x + av.x*dx*inv + bv.x;
    o.y = hv.y + av.y*dy*inv + bv.y;
    o.z = hv.z + av.z*dz*inv + bv.z;
    o.w = hv.w + av.w*dw*inv + bv.w;
    ((float4*)(out + (size_t)row*DD))[tid] = o;
}

// ---------------------------------------------------------------------------
extern "C" void kernel_launch(void* const* d_in, const int* in_sizes, int n_in,
                              void* d_out, int out_size)
{
    const float* img       = (const float*)d_in[0];
    const float* title     = (const float*)d_in[1];
    const int*   mask      = (const int*)  d_in[2];
    const float* scale_img = (const float*)d_in[3];
    const float* scale_tit = (const float*)d_in[4];
    const float* w_proj    = (const float*)d_in[5];
    const float* b_proj    = (const float*)d_in[6];
    const float* w1_img    = (const float*)d_in[7];
    const float* b1_img    = (const float*)d_in[8];
    const float* w2_img    = (const float*)d_in[9];
    const float* b2_img    = (const float*)d_in[10];
    const float* w1_tit    = (const float*)d_in[11];
    const float* b1_tit    = (const float*)d_in[12];
    const float* w2_tit    = (const float*)d_in[13];
    const float* b2_tit    = (const float*)d_in[14];
    const float* ln_a_img  = (const float*)d_in[15];
    const float* ln_b_img  = (const float*)d_in[16];
    const float* ln_a_tit  = (const float*)d_in[17];
    const float* ln_b_tit  = (const float*)d_in[18];
    float* out = (float*)d_out;

    float *hidpre, *hid, *act;
    cudaGetSymbolAddress((void**)&hidpre, g_hidpre);
    cudaGetSymbolAddress((void**)&hid,    g_hid);
    cudaGetSymbolAddress((void**)&act,    g_act);

    const int attn_smem = (PP*STRIDE + TT*STRIDE + 2*HH*PP*TT + HH*PP + HH*TT)*4 + TT*4;
    cudaFuncSetAttribute(attn_kernel, cudaFuncAttributeMaxDynamicSharedMemorySize, attn_smem);

    // 0) zero pad rows of hidpre (rows 55200..55296) for deterministic pads
    zero_pad_k<<<(M_ALLP - M_ALL)*DD/512, 512>>>(hidpre);

    // 1) attention -> hid_pre (img rows [0,16000), tit rows [16000,55200))
    attn_kernel<<<NBL, 256, attn_smem>>>(img, title, mask, scale_img, scale_tit, hidpre);

    // 2) shared projection (combined matrix), bf16x3 mma.sync
    mma_gemm_k<false><<<dim3(DD/128, M_ALLP/128), 256>>>(
        hidpre, w_proj, b_proj, hid, DD, DD);

    // 3) FFN1 + gelu
    mma_gemm_k<true><<<dim3(DFF/128, M_IMG/128), 256>>>(
        hid, w1_img, b1_img, act, DD, DFF);
    mma_gemm_k<true><<<dim3(DFF/128, M_TITP/128), 256>>>(
        hid + (size_t)M_IMG*DD, w1_tit, b1_tit, act + (size_t)M_IMG*DFF, DD, DFF);

    // 4) FFN2 -> reuse hidpre as ffn output buffer
    mma_gemm_k<false><<<dim3(DD/128, M_IMG/128), 256>>>(
        act, w2_img, b2_img, hidpre, DFF, DD);
    mma_gemm_k<false><<<dim3(DD/128, M_TITP/128), 256>>>(
        act + (size_t)M_IMG*DFF, w2_tit, b2_tit, hidpre + (size_t)M_IMG*DD, DFF, DD);

    // 5) residual + layernorm -> out
    ln_res_kernel<<<M_ALL, 128>>>(hidpre, hid, ln_a_img, ln_b_img, ln_a_tit, ln_b_tit, out);
}

// round 16
// speedup vs baseline: 2.6796x; 1.0662x over previous
#include <cuda_runtime.h>
#include <cuda_bf16.h>
#include <math.h>
#include <stdint.h>

#define BB 16
#define LL 50
#define PP 49
#define TT 20
#define DD 512
#define HH 8
#define DHH 64
#define DFF 2048
#define NBL (BB*LL)            // 800
#define M_IMG (NBL*TT)         // 16000
#define M_TIT (NBL*PP)         // 39200
#define M_ALL (M_IMG+M_TIT)    // 55200
#define M_TITP 39296
#define M_ALLP 55296           // 432*128
#define NEGV (-1000000000.0f)
#define STRIDE 516
#define LDA 40                 // smem row stride in bf16 elems (80B = 5*16B)

// weight split offsets (elements)
#define W_PROJ_OFF 0
#define W_PROJ_N (DD*DD)
#define W1I_OFF (W_PROJ_OFF + W_PROJ_N)
#define W1_N (DFF*DD)
#define W1T_OFF (W1I_OFF + W1_N)
#define W2I_OFF (W1T_OFF + W1_N)
#define W2_N (DD*DFF)
#define W2T_OFF (W2I_OFF + W2_N)
#define W_TOT (W2T_OFF + W2_N)

// ---------------- persistent scratch (device globals) -----------------------
__device__ unsigned short g_whi[W_TOT];
__device__ unsigned short g_wlo[W_TOT];
__device__ unsigned short g_xhi[(size_t)M_ALLP*DD];   // attn out hi
__device__ unsigned short g_xlo[(size_t)M_ALLP*DD];   // attn out lo
__device__ float          g_hid[(size_t)M_ALLP*DD];   // post-proj fp32 (residual)
__device__ unsigned short g_hhi[(size_t)M_ALLP*DD];   // post-proj hi
__device__ unsigned short g_hlo[(size_t)M_ALLP*DD];   // post-proj lo
__device__ unsigned short g_ahi[(size_t)M_ALLP*DFF];  // ffn1 act hi
__device__ unsigned short g_alo[(size_t)M_ALLP*DFF];  // ffn1 act lo
__device__ float          g_ffn[(size_t)M_ALLP*DD];   // ffn2 out fp32

// ---------------- helpers ----------------------------------------------------
__device__ __forceinline__ uint32_t smem_u32(const void* p){
    uint32_t a;
    asm("{ .reg .u64 t; cvta.to.shared.u64 t, %1; cvt.u32.u64 %0, t; }"
        : "=r"(a) : "l"(p));
    return a;
}
__device__ __forceinline__ void ldsm_x4(uint32_t addr, uint32_t& r0, uint32_t& r1,
                                        uint32_t& r2, uint32_t& r3){
    asm volatile("ldmatrix.sync.aligned.m8n8.x4.shared.b16 {%0,%1,%2,%3}, [%4];"
                 : "=r"(r0), "=r"(r1), "=r"(r2), "=r"(r3) : "r"(addr));
}
__device__ __forceinline__ void mma16816(float* c, const uint32_t* a, const uint32_t* b){
    asm volatile(
        "mma.sync.aligned.m16n8k16.row.col.f32.bf16.bf16.f32 "
        "{%0,%1,%2,%3}, {%4,%5,%6,%7}, {%8,%9}, {%0,%1,%2,%3};"
        : "+f"(c[0]), "+f"(c[1]), "+f"(c[2]), "+f"(c[3])
        : "r"(a[0]), "r"(a[1]), "r"(a[2]), "r"(a[3]), "r"(b[0]), "r"(b[1]));
}
__device__ __forceinline__ void cpa16(uint32_t dst, const void* src){
    asm volatile("cp.async.ca.shared.global [%0], [%1], 16;" :: "r"(dst), "l"(src));
}
__device__ __forceinline__ void split2(float x, unsigned short& h, unsigned short& l){
    __nv_bfloat16 bh = __float2bfloat16(x);
    float r = x - __bfloat162float(bh);
    __nv_bfloat16 bl = __float2bfloat16(r);
    h = *(unsigned short*)&bh;
    l = *(unsigned short*)&bl;
}
__device__ __forceinline__ float gelu_tanh_f(float x){
    return 0.5f*x*(1.f + tanhf(0.7978845608028654f*(x + 0.044715f*x*x*x)));
}

// ---------------- weight split: fp32 -> bf16 hi/lo ---------------------------
__global__ __launch_bounds__(256) void split_w_k(
    const float* __restrict__ w, unsigned short* __restrict__ hi,
    unsigned short* __restrict__ lo, int n4)
{
    int i = blockIdx.x*256 + threadIdx.x;
    if (i >= n4) return;
    float4 v = ((const float4*)w)[i];
    unsigned short h0,h1,h2,h3,l0,l1,l2,l3;
    split2(v.x,h0,l0); split2(v.y,h1,l1); split2(v.z,h2,l2); split2(v.w,h3,l3);
    uint2 H, L;
    H.x = (uint32_t)h0 | ((uint32_t)h1<<16); H.y = (uint32_t)h2 | ((uint32_t)h3<<16);
    L.x = (uint32_t)l0 | ((uint32_t)l1<<16); L.y = (uint32_t)l2 | ((uint32_t)l3<<16);
    *(uint2*)(hi + (size_t)i*4) = H;
    *(uint2*)(lo + (size_t)i*4) = L;
}

// ---------------- zero pad rows of attn output (bf16) ------------------------
__global__ void zero_pad_k(unsigned short* hi, unsigned short* lo){
    size_t i = (size_t)blockIdx.x*512 + threadIdx.x;
    hi[(size_t)M_ALL*DD + i] = 0;
    lo[(size_t)M_ALL*DD + i] = 0;
}

// ---------------- bf16x3 GEMM v2: all-bf16 inputs, cp.async double-buffer ----
// C = A[M,K] @ B[N,K]^T + bias. CTA 128x128, BK=32, 8 warps (4M x 2N).
// MODE bits: 1=gelu, 2=write fp32 C, 4=write bf16 hi/lo
#define BUF_BYTES 40960   // 4 arrays x 128*LDA ushorts
#define ARR_BYTES 10240

template<int MODE>
__global__ __launch_bounds__(256, 2) void mma_gemm2_k(
    const unsigned short* __restrict__ Ahi, const unsigned short* __restrict__ Alo,
    const unsigned short* __restrict__ Bhi, const unsigned short* __restrict__ Blo,
    const float* __restrict__ bias,
    float* __restrict__ C, unsigned short* __restrict__ Chi,
    unsigned short* __restrict__ Clo,
    int K, int ldc)
{
    extern __shared__ unsigned short smv2[];
    uint32_t smb = smem_u32(smv2);

    int tid = threadIdx.x;
    int lane = tid & 31, wid = tid >> 5;
    int wm = wid & 3, wn = wid >> 2;
    int g = lane >> 3, r = lane & 7;

    uint32_t a_off = (uint32_t)((wm*32 + ((g & 1) << 3) + r)*LDA + ((g >> 1) << 3)) * 2u;
    uint32_t b_off = (uint32_t)((wn*64 + ((g & 2) << 2) + r)*LDA + ((g & 1) << 3)) * 2u;

    size_t aBase = (size_t)(blockIdx.y << 7) * K;
    size_t bBase = (size_t)(blockIdx.x << 7) * K;

    float acc[2][8][4];
    #pragma unroll
    for (int mt=0; mt<2; mt++)
        #pragma unroll
        for (int nt=0; nt<8; nt++)
            #pragma unroll
            for (int j=0; j<4; j++) acc[mt][nt][j] = 0.f;

    const int NC = K >> 5;

    // ---- cp.async issue for one chunk into buffer b ----
    #define ISSUE8(bb, k0_) do { \
        uint32_t bufb_ = smb + (uint32_t)(bb)*BUF_BYTES; \
        _Pragma("unroll") \
        for (int h_=0; h_<2; h_++){ \
            int idx_ = tid + (h_<<8); \
            int row_ = idx_ >> 2, seg_ = idx_ & 3; \
            uint32_t doff_ = (uint32_t)(row_*LDA + seg_*8) * 2u; \
            size_t ao_ = aBase + (size_t)row_*K + (k0_) + seg_*8; \
            size_t bo_ = bBase + (size_t)row_*K + (k0_) + seg_*8; \
            cpa16(bufb_ + 0*ARR_BYTES + doff_, Ahi + ao_); \
            cpa16(bufb_ + 1*ARR_BYTES + doff_, Alo + ao_); \
            cpa16(bufb_ + 2*ARR_BYTES + doff_, Bhi + bo_); \
            cpa16(bufb_ + 3*ARR_BYTES + doff_, Blo + bo_); \
        } \
        asm volatile("cp.async.commit_group;"); \
    } while(0)

    ISSUE8(0, 0);

    for (int ch = 0; ch < NC; ch++){
        int b = ch & 1;
        if (ch + 1 < NC){
            ISSUE8(b^1, (ch+1) << 5);
            asm volatile("cp.async.wait_group 1;");
        } else {
            asm volatile("cp.async.wait_group 0;");
        }
        __syncthreads();

        uint32_t bufb = smb + (uint32_t)b*BUF_BYTES;
        uint32_t aHi = bufb + 0*ARR_BYTES + a_off;
        uint32_t aLo = bufb + 1*ARR_BYTES + a_off;
        uint32_t bHi = bufb + 2*ARR_BYTES + b_off;
        uint32_t bLo = bufb + 3*ARR_BYTES + b_off;

        #pragma unroll
        for (int ks=0; ks<2; ks++){
            uint32_t kofs = (uint32_t)ks * 32u;
            uint32_t a_h[2][4], a_l[2][4];
            ldsm_x4(aHi + kofs,        a_h[0][0], a_h[0][1], a_h[0][2], a_h[0][3]);
            ldsm_x4(aHi + kofs + 1280, a_h[1][0], a_h[1][1], a_h[1][2], a_h[1][3]);
            ldsm_x4(aLo + kofs,        a_l[0][0], a_l[0][1], a_l[0][2], a_l[0][3]);
            ldsm_x4(aLo + kofs + 1280, a_l[1][0], a_l[1][1], a_l[1][2], a_l[1][3]);

            #pragma unroll
            for (int nh=0; nh<2; nh++){
                uint32_t b_h[4][2], b_l[4][2];
                #pragma unroll
                for (int p=0; p<2; p++){
                    uint32_t boff2 = kofs + (uint32_t)(nh*2 + p) * 1280u;
                    ldsm_x4(bHi + boff2, b_h[2*p][0], b_h[2*p][1], b_h[2*p+1][0], b_h[2*p+1][1]);
                    ldsm_x4(bLo + boff2, b_l[2*p][0], b_l[2*p][1], b_l[2*p+1][0], b_l[2*p+1][1]);
                }
                #pragma unroll
                for (int mt=0; mt<2; mt++)
                    #pragma unroll
                    for (int ntl=0; ntl<4; ntl++){
                        float* c = acc[mt][nh*4 + ntl];
                        mma16816(c, a_h[mt], b_h[ntl]);
                        mma16816(c, a_h[mt], b_l[ntl]);
                        mma16816(c, a_l[mt], b_h[ntl]);
                    }
            }
        }
        __syncthreads();
    }

    // ---- epilogue ----
    int mbase = (blockIdx.y << 7) + wm*32;
    int nbase = (blockIdx.x << 7) + wn*64;
    int qr = lane >> 2;
    int qc = (lane & 3) << 1;
    #pragma unroll
    for (int mt=0; mt<2; mt++){
        #pragma unroll
        for (int nt=0; nt<8; nt++){
            int row = mbase + mt*16 + qr;
            int col = nbase + nt*8 + qc;
            float b0 = bias[col], b1 = bias[col+1];
            float v0 = acc[mt][nt][0] + b0;
            float v1 = acc[mt][nt][1] + b1;
            float v2 = acc[mt][nt][2] + b0;
            float v3 = acc[mt][nt][3] + b1;
            if (MODE & 1){
                v0 = gelu_tanh_f(v0); v1 = gelu_tanh_f(v1);
                v2 = gelu_tanh_f(v2); v3 = gelu_tanh_f(v3);
            }
            size_t o0 = (size_t)row*ldc + col;
            size_t o1 = (size_t)(row+8)*ldc + col;
            if (MODE & 2){
                *(float2*)(C + o0) = make_float2(v0, v1);
                *(float2*)(C + o1) = make_float2(v2, v3);
            }
            if (MODE & 4){
                unsigned short h0,h1,h2,h3,l0,l1,l2,l3;
                split2(v0,h0,l0); split2(v1,h1,l1); split2(v2,h2,l2); split2(v3,h3,l3);
                ushort2 H01; H01.x=h0; H01.y=h1;
                ushort2 L01; L01.x=l0; L01.y=l1;
                ushort2 H23; H23.x=h2; H23.y=h3;
                ushort2 L23; L23.x=l2; L23.y=l3;
                *(ushort2*)(Chi + o0) = H01;
                *(ushort2*)(Clo + o0) = L01;
                *(ushort2*)(Chi + o1) = H23;
                *(ushort2*)(Clo + o1) = L23;
            }
        }
    }
    #undef ISSUE8
}

// ---------------- Kernel 1: per-(b,l) cross attention -> bf16 hi/lo ---------
__global__ __launch_bounds__(256) void attn_kernel(
    const float* __restrict__ img, const float* __restrict__ title,
    const int* __restrict__ mask, const float* __restrict__ scale_img,
    const float* __restrict__ scale_tit,
    unsigned short* __restrict__ xhi, unsigned short* __restrict__ xlo)
{
    extern __shared__ float sm[];
    float* s_img = sm;
    float* s_tit = s_img + PP*STRIDE;
    float* s_raw = s_tit + TT*STRIDE;
    float* s_p   = s_raw + HH*PP*TT;
    float* s_si  = s_p  + HH*PP*TT;
    float* s_st  = s_si + HH*PP;
    int*   s_mask= (int*)(s_st + HH*TT);

    int bl  = blockIdx.x;
    int tid = threadIdx.x;

    const float* gi = img + (size_t)bl*PP*DD;
    for (int i = tid; i < PP*(DD/4); i += 256){
        int r = i >> 7, c = i & 127;
        float4 v = ((const float4*)(gi + (size_t)r*DD))[c];
        *(float4*)(s_img + r*STRIDE + c*4) = v;
    }
    const float* gt = title + (size_t)bl*TT*DD;
    for (int i = tid; i < TT*(DD/4); i += 256){
        int r = i >> 7, c = i & 127;
        float4 v = ((const float4*)(gt + (size_t)r*DD))[c];
        *(float4*)(s_tit + r*STRIDE + c*4) = v;
    }
    for (int i = tid; i < HH*PP; i += 256) s_si[i] = scale_img[i];
    for (int i = tid; i < HH*TT; i += 256) s_st[i] = scale_tit[i];
    if (tid < TT) s_mask[tid] = mask[bl*TT + tid];
    __syncthreads();

    for (int pair = tid; pair < HH*PP; pair += 256){
        int h = pair / PP, p = pair % PP;
        float acc[TT];
        #pragma unroll
        for (int t=0;t<TT;t++) acc[t]=0.f;
        const float* ib = s_img + p*STRIDE + h*DHH;
        const float* tb = s_tit + h*DHH;
        #pragma unroll 4
        for (int d=0; d<DHH; d++){
            float a = ib[d];
            #pragma unroll
            for (int t=0;t<TT;t++) acc[t] += a * tb[t*STRIDE + d];
        }
        float* rw = s_raw + pair*TT;
        #pragma unroll
        for (int t=0;t<TT;t++) rw[t] = acc[t]*0.125f;
    }
    __syncthreads();

    for (int pair = tid; pair < HH*PP; pair += 256){
        float sc = s_si[pair];
        const float* rw = s_raw + pair*TT;
        float v[TT]; float m = -3.4e38f;
        #pragma unroll
        for (int t=0;t<TT;t++){
            v[t] = (s_mask[t]==0) ? NEGV : rw[t]*sc;
            m = fmaxf(m, v[t]);
        }
        float s = 0.f;
        #pragma unroll
        for (int t=0;t<TT;t++){ v[t] = expf(v[t]-m); s += v[t]; }
        float inv = 1.f/s;
        float* pw = s_p + pair*TT;
        #pragma unroll
        for (int t=0;t<TT;t++) pw[t] = v[t]*inv;
    }
    __syncthreads();

    for (int idx = tid; idx < PP*(DD/4); idx += 256){
        int p = idx >> 7, c = idx & 127;
        int col = c*4; int h = col >> 6;
        const float* pw = s_p + (h*PP + p)*TT;
        float4 acc = make_float4(0.f,0.f,0.f,0.f);
        #pragma unroll
        for (int t=0;t<TT;t++){
            float w = pw[t];
            float4 v = *(const float4*)(s_tit + t*STRIDE + col);
            acc.x += w*v.x; acc.y += w*v.y; acc.z += w*v.z; acc.w += w*v.w;
        }
        unsigned short h0,h1,h2,h3,l0,l1,l2,l3;
        split2(acc.x,h0,l0); split2(acc.y,h1,l1); split2(acc.z,h2,l2); split2(acc.w,h3,l3);
        uint2 H, L;
        H.x = (uint32_t)h0 | ((uint32_t)h1<<16); H.y = (uint32_t)h2 | ((uint32_t)h3<<16);
        L.x = (uint32_t)l0 | ((uint32_t)l1<<16); L.y = (uint32_t)l2 | ((uint32_t)l3<<16);
        size_t o = (size_t)(M_IMG + bl*PP + p)*DD + col;
        *(uint2*)(xhi + o) = H;
        *(uint2*)(xlo + o) = L;
    }
    __syncthreads();

    for (int idx = tid; idx < HH*TT; idx += 256){
        int h = idx / TT, t = idx % TT;
        float sc = s_st[idx];
        bool mz = (s_mask[t]==0);
        const float* rw = s_raw + h*PP*TT + t;
        float m = -3.4e38f;
        for (int p=0;p<PP;p++){
            float v = mz ? NEGV : rw[p*TT]*sc;
            m = fmaxf(m, v);
        }
        float* pw = s_p + (h*TT + t)*PP;
        float s = 0.f;
        for (int p=0;p<PP;p++){
            float v = mz ? NEGV : rw[p*TT]*sc;
            float e = expf(v-m);
            pw[p] = e; s += e;
        }
        float inv = 1.f/s;
        for (int p=0;p<PP;p++) pw[p] *= inv;
    }
    __syncthreads();

    for (int idx = tid; idx < TT*(DD/4); idx += 256){
        int t = idx >> 7, c = idx & 127;
        int col = c*4; int h = col >> 6;
        const float* pw = s_p + (h*TT + t)*PP;
        float4 acc = make_float4(0.f,0.f,0.f,0.f);
        for (int p=0;p<PP;p++){
            float w = pw[p];
            float4 v = *(const float4*)(s_img + p*STRIDE + col);
            acc.x += w*v.x; acc.y += w*v.y; acc.z += w*v.z; acc.w += w*v.w;
        }
        unsigned short h0,h1,h2,h3,l0,l1,l2,l3;
        split2(acc.x,h0,l0); split2(acc.y,h1,l1); split2(acc.z,h2,l2); split2(acc.w,h3,l3);
        uint2 H, L;
        H.x = (uint32_t)h0 | ((uint32_t)h1<<16); H.y = (uint32_t)h2 | ((uint32_t)h3<<16);
        L.x = (uint32_t)l0 | ((uint32_t)l1<<16); L.y = (uint32_t)l2 | ((uint32_t)l3<<16);
        size_t o = (size_t)(bl*TT + t)*DD + col;
        *(uint2*)(xhi + o) = H;
        *(uint2*)(xlo + o) = L;
    }
}

// ---------------- Kernel 3: residual + layernorm ----------------------------
__device__ __forceinline__ float blockReduce128(float v){
    __shared__ float red[4];
    int lane = threadIdx.x & 31, w = threadIdx.x >> 5;
    #pragma unroll
    for (int o=16;o>0;o>>=1) v += __shfl_down_sync(0xffffffffu, v, o);
    if (lane==0) red[w]=v;
    __syncthreads();
    float r = red[0]+red[1]+red[2]+red[3];
    __syncthreads();
    return r;
}

__global__ __launch_bounds__(128) void ln_res_kernel(
    const float* __restrict__ ffn, const float* __restrict__ hid,
    const float* __restrict__ a_img, const float* __restrict__ b_img,
    const float* __restrict__ a_tit, const float* __restrict__ b_tit,
    float* __restrict__ out)
{
    int row = blockIdx.x; int tid = threadIdx.x;
    float4 v = ((const float4*)(ffn + (size_t)row*DD))[tid];
    float s = v.x+v.y+v.z+v.w;
    float tot = blockReduce128(s);
    float mean = tot * (1.f/DD);
    float dx=v.x-mean, dy=v.y-mean, dz=v.z-mean, dw=v.w-mean;
    float sq = dx*dx+dy*dy+dz*dz+dw*dw;
    float tsq = blockReduce128(sq);
    float var = tsq * (1.f/(DD-1));
    float inv = 1.f/(sqrtf(var)+1e-6f);
    const float* ga = (row < M_IMG)? a_img : a_tit;
    const float* gb = (row < M_IMG)? b_img : b_tit;
    float4 av = ((const float4*)ga)[tid];
    float4 bv = ((const float4*)gb)[tid];
    float4 hv = ((const float4*)(hid + (size_t)row*DD))[tid];
    float4 o;
    o.x = hv.x + av.x*dx*inv + bv.x;
    o.y = hv.y + av.y*dy*inv + bv.y;
    o.z = hv.z + av.z*dz*inv + bv.z;
    o.w = hv.w + av.w*dw*inv + bv.w;
    ((float4*)(out + (size_t)row*DD))[tid] = o;
}

// ---------------------------------------------------------------------------
extern "C" void kernel_launch(void* const* d_in, const int* in_sizes, int n_in,
                              void* d_out, int out_size)
{
    const float* img       = (const float*)d_in[0];
    const float* title     = (const float*)d_in[1];
    const int*   mask      = (const int*)  d_in[2];
    const float* scale_img = (const float*)d_in[3];
    const float* scale_tit = (const float*)d_in[4];
    const float* w_proj    = (const float*)d_in[5];
    const float* b_proj    = (const float*)d_in[6];
    const float* w1_img    = (const float*)d_in[7];
    const float* b1_img    = (const float*)d_in[8];
    const float* w2_img    = (const float*)d_in[9];
    const float* b2_img    = (const float*)d_in[10];
    const float* w1_tit    = (const float*)d_in[11];
    const float* b1_tit    = (const float*)d_in[12];
    const float* w2_tit    = (const float*)d_in[13];
    const float* b2_tit    = (const float*)d_in[14];
    const float* ln_a_img  = (const float*)d_in[15];
    const float* ln_b_img  = (const float*)d_in[16];
    const float* ln_a_tit  = (const float*)d_in[17];
    const float* ln_b_tit  = (const float*)d_in[18];
    float* out = (float*)d_out;

    unsigned short *whi, *wlo, *xhi, *xlo, *hhi, *hlo, *ahi, *alo;
    float *hid, *ffn;
    cudaGetSymbolAddress((void**)&whi, g_whi);
    cudaGetSymbolAddress((void**)&wlo, g_wlo);
    cudaGetSymbolAddress((void**)&xhi, g_xhi);
    cudaGetSymbolAddress((void**)&xlo, g_xlo);
    cudaGetSymbolAddress((void**)&hhi, g_hhi);
    cudaGetSymbolAddress((void**)&hlo, g_hlo);
    cudaGetSymbolAddress((void**)&ahi, g_ahi);
    cudaGetSymbolAddress((void**)&alo, g_alo);
    cudaGetSymbolAddress((void**)&hid, g_hid);
    cudaGetSymbolAddress((void**)&ffn, g_ffn);

    const int attn_smem = (PP*STRIDE + TT*STRIDE + 2*HH*PP*TT + HH*PP + HH*TT)*4 + TT*4;
    cudaFuncSetAttribute(attn_kernel, cudaFuncAttributeMaxDynamicSharedMemorySize, attn_smem);
    cudaFuncSetAttribute(mma_gemm2_k<6>, cudaFuncAttributeMaxDynamicSharedMemorySize, 2*BUF_BYTES);
    cudaFuncSetAttribute(mma_gemm2_k<5>, cudaFuncAttributeMaxDynamicSharedMemorySize, 2*BUF_BYTES);
    cudaFuncSetAttribute(mma_gemm2_k<2>, cudaFuncAttributeMaxDynamicSharedMemorySize, 2*BUF_BYTES);

    // 0) one-time weight splits (re-done each call; ~10us total)
    split_w_k<<<W_PROJ_N/1024, 256>>>(w_proj, whi + W_PROJ_OFF, wlo + W_PROJ_OFF, W_PROJ_N/4);
    split_w_k<<<W1_N/1024, 256>>>(w1_img, whi + W1I_OFF, wlo + W1I_OFF, W1_N/4);
    split_w_k<<<W1_N/1024, 256>>>(w1_tit, whi + W1T_OFF, wlo + W1T_OFF, W1_N/4);
    split_w_k<<<W2_N/1024, 256>>>(w2_img, whi + W2I_OFF, wlo + W2I_OFF, W2_N/4);
    split_w_k<<<W2_N/1024, 256>>>(w2_tit, whi + W2T_OFF, wlo + W2T_OFF, W2_N/4);

    // zero pad rows of attn output
    zero_pad_k<<<(M_ALLP - M_ALL)*DD/512, 512>>>(xhi, xlo);

    // 1) attention -> xhi/xlo
    attn_kernel<<<NBL, 256, attn_smem>>>(img, title, mask, scale_img, scale_tit, xhi, xlo);

    // 2) shared projection: writes hid fp32 + hhi/hlo bf16
    mma_gemm2_k<6><<<dim3(DD/128, M_ALLP/128), 256, 2*BUF_BYTES>>>(
        xhi, xlo, whi + W_PROJ_OFF, wlo + W_PROJ_OFF, b_proj,
        hid, hhi, hlo, DD, DD);

    // 3) FFN1 + gelu: writes ahi/alo bf16 only
    mma_gemm2_k<5><<<dim3(DFF/128, M_IMG/128), 256, 2*BUF_BYTES>>>(
        hhi, hlo, whi + W1I_OFF, wlo + W1I_OFF, b1_img,
        (float*)0, ahi, alo, DD, DFF);
    mma_gemm2_k<5><<<dim3(DFF/128, M_TITP/128), 256, 2*BUF_BYTES>>>(
        hhi + (size_t)M_IMG*DD, hlo + (size_t)M_IMG*DD, whi + W1T_OFF, wlo + W1T_OFF, b1_tit,
        (float*)0, ahi + (size_t)M_IMG*DFF, alo + (size_t)M_IMG*DFF, DD, DFF);

    // 4) FFN2: writes ffn fp32
    mma_gemm2_k<2><<<dim3(DD/128, M_IMG/128), 256, 2*BUF_BYTES>>>(
        ahi, alo, whi + W2I_OFF, wlo + W2I_OFF, b2_img,
        ffn, (unsigned short*)0, (unsigned short*)0, DFF, DD);
    mma_gemm2_k<2><<<dim3(DD/128, M_TITP/128), 256, 2*BUF_BYTES>>>(
        ahi + (size_t)M_IMG*DFF, alo + (size_t)M_IMG*DFF, whi + W2T_OFF, wlo + W2T_OFF, b2_tit,
        ffn + (size_t)M_IMG*DD, (unsigned short*)0, (unsigned short*)0, DFF, DD);

    // 5) residual + layernorm -> out
    ln_res_kernel<<<M_ALL, 128>>>(ffn, hid, ln_a_img, ln_b_img, ln_a_tit, ln_b_tit, out);
}